// round 14
// baseline (speedup 1.0000x reference)
#include <cuda_runtime.h>
#include <cuda_fp16.h>
#include <cstdint>

#define NNODE 10000
#define BNUM  4
#define DDIM  128
#define ECAP  262144
#define ND    (NNODE*DDIM)
#define SLOPE 0.01f
#define GEMMX 157   // (NNODE+63)/64
#define EBLK  740   // edge grid: 148 SMs x 5 blocks (grid-stride over nodes)

// ---------------- scratch (device globals; no allocation) ----------------
__device__ __align__(16) __half g_xh[BNUM*ND];   // layer activations (fp16, per-batch)
__device__ __align__(16) __half g_strh[ND];      // strucEmb fp16
__device__ __align__(16) __half g_Wh[4*DDIM*DDIM]; // gatW[0..2], W2 as fp16
__device__ __align__(16) __half g_h[BNUM*ND];    // per-layer hidden h (fp16, per-batch)
__device__ __align__(16) float g_asrcT[NNODE*4]; // [n][b] transposed logits
__device__ __align__(16) float g_adstT[NNODE*4];
__device__ int   g_offs[NNODE+1];
__device__ int   g_cur[NNODE];    // ==0 at entry of every execution (reset by edge0 tail)
__device__ int   g_srcs[ECAP];
__device__ float g_wnsW[3*DDIM];
__device__ float g_bnsW[3*DDIM];
__device__ float g_semb[BNUM*DDIM];
__device__ float g_rs[BNUM];

// ---------------- mma / async helpers ----------------
__device__ __forceinline__ uint32_t su(const void* p) {
    return (uint32_t)__cvta_generic_to_shared(p);
}
__device__ __forceinline__ void cpa16(uint32_t dst, const void* src) {
    asm volatile("cp.async.cg.shared.global [%0], [%1], 16;" :: "r"(dst), "l"(src));
}
__device__ __forceinline__ void ldsm4(uint32_t& r0, uint32_t& r1, uint32_t& r2,
                                      uint32_t& r3, uint32_t addr) {
    asm volatile("ldmatrix.sync.aligned.m8n8.x4.shared.b16 {%0,%1,%2,%3}, [%4];"
                 : "=r"(r0), "=r"(r1), "=r"(r2), "=r"(r3) : "r"(addr));
}
__device__ __forceinline__ void ldsm4t(uint32_t& r0, uint32_t& r1, uint32_t& r2,
                                       uint32_t& r3, uint32_t addr) {
    asm volatile("ldmatrix.sync.aligned.m8n8.x4.trans.shared.b16 {%0,%1,%2,%3}, [%4];"
                 : "=r"(r0), "=r"(r1), "=r"(r2), "=r"(r3) : "r"(addr));
}
__device__ __forceinline__ void mma16816(float* c, uint32_t a0, uint32_t a1,
                                         uint32_t a2, uint32_t a3,
                                         uint32_t b0, uint32_t b1) {
    asm volatile(
        "mma.sync.aligned.m16n8k16.row.col.f32.f16.f16.f32 "
        "{%0,%1,%2,%3}, {%4,%5,%6,%7}, {%8,%9}, {%0,%1,%2,%3};"
        : "+f"(c[0]), "+f"(c[1]), "+f"(c[2]), "+f"(c[3])
        : "r"(a0), "r"(a1), "r"(a2), "r"(a3), "r"(b0), "r"(b1));
}

// ---------------- init: prep + semb zero + fp16 conversions + HIST fused ----
__global__ void k_init(const float* __restrict__ W, const float* __restrict__ W2,
                       const float* __restrict__ Wns, const float* __restrict__ bns,
                       const float* __restrict__ struc,
                       const int* __restrict__ ei, int Etot) {
    int bb = blockIdx.x;
    if (bb < 3) {
        int l = bb, c = threadIdx.x;
        if (c < DDIM) {
            const float* Wl = W + l*DDIM*DDIM;
            float aw = 0.f, ab = 0.f;
            for (int k = 0; k < DDIM; k++) {
                float w = Wl[k*DDIM + c];
                aw += Wns[l*DDIM + k]*w;
                ab += bns[l*DDIM + k]*w;
            }
            g_wnsW[l*DDIM + c] = aw;
            g_bnsW[l*DDIM + c] = ab;
        }
    } else if (bb < 5) {
        int i = (bb - 3)*256 + threadIdx.x;
        if (i < BNUM*DDIM) g_semb[i] = 0.f;
    } else if (bb < 69) {
        int i0 = (bb - 5)*1024 + threadIdx.x*4;
        int m = i0 >> 14, off = i0 & 16383;
        const float* src = (m < 3) ? (W + m*16384 + off) : (W2 + off);
        float4 v = *(const float4*)src;
        union { __half2 h[2]; uint2 u; } cv;
        cv.h[0] = __floats2half2_rn(v.x, v.y);
        cv.h[1] = __floats2half2_rn(v.z, v.w);
        *(uint2*)&g_Wh[i0] = cv.u;
    } else if (bb < 1319) {
        int i0 = (bb - 69)*1024 + threadIdx.x*4;
        if (i0 < ND) {
            float4 v = *(const float4*)(struc + i0);
            union { __half2 h[2]; uint2 u; } cv;
            cv.h[0] = __floats2half2_rn(v.x, v.y);
            cv.h[1] = __floats2half2_rn(v.z, v.w);
            *(uint2*)&g_strh[i0] = cv.u;
        }
    } else {
        // histogram role (g_cur == 0 at entry: static init / edge0-tail reset)
        int e = (bb - 1319)*256 + threadIdx.x;
        if (e < Etot) atomicAdd(&g_cur[ei[Etot + e]], 1);
    }
}

// ---------------- CSR scan ----------------
__global__ void k_scan(int Etot) {
    __shared__ int sh[1024];
    const int ITEMS = 10;
    int t = threadIdx.x;
    int base = t*ITEMS;
    int loc[ITEMS]; int sum = 0;
#pragma unroll
    for (int i = 0; i < ITEMS; i++) {
        int idx = base + i;
        int v = (idx < NNODE) ? g_cur[idx] : 0;
        loc[i] = sum; sum += v;
    }
    sh[t] = sum; __syncthreads();
    for (int off = 1; off < 1024; off <<= 1) {
        int v = (t >= off) ? sh[t-off] : 0;
        __syncthreads();
        sh[t] += v;
        __syncthreads();
    }
    int pre = t ? sh[t-1] : 0;
#pragma unroll
    for (int i = 0; i < ITEMS; i++) {
        int idx = base + i;
        if (idx < NNODE) { int o = pre + loc[i]; g_offs[idx] = o; g_cur[idx] = o; }
    }
    if (t == 1023) g_offs[NNODE] = sh[1023];
}

// ---------------- HMMA GEMM (64x128 tile, fp16 in / fp32 acc) ----------------
// Software-pipelined: cp.async group{A0,B0}, group{A1}; B1 prefetched to regs
// during mma0. Layer-0 launch carries extra blocks doing CSR scatter.
#define AS_STR 72
#define BS_STR 136
template<int MODE>
__global__ void __launch_bounds__(256)
k_gemm(int widx, const float* __restrict__ state,
       const float* __restrict__ attS, const float* __restrict__ attD,
       const float* __restrict__ b2, const float* __restrict__ W3,
       float* __restrict__ out,
       const int* __restrict__ ei, int Etot) {
    if (blockIdx.x >= GEMMX) {
        // scatter role (only present on the layer-0 launch; needs k_scan done)
        int e = ((blockIdx.x - GEMMX)*4 + blockIdx.y)*256 + threadIdx.x;
        if (e < Etot) {
            int d = ei[Etot + e];
            int pos = atomicAdd(&g_cur[d], 1);
            g_srcs[pos] = ei[e];
        }
        return;
    }
    __shared__ __align__(16) unsigned char smraw[37888];
    __half* As = (__half*)smraw;                    // [2][64][72]  (double buffer)
    __half* Bs = (__half*)(smraw + 18432);          // [64][136]
    float*  acc_s = (float*)smraw;                  // [64][132] (reused)
    float*  pb = (float*)(smraw + 35840);           // 512 floats of params

    const int tid = threadIdx.x;
    const int lane = tid & 31, warp = tid >> 5;
    const int warpM = warp & 3, warpN = warp >> 2;
    const int b = blockIdx.y;
    const int rowbase = blockIdx.x * 64;

    const __half* xa = (widx == 0) ? g_strh : g_xh;
    const size_t xboff = (widx == 0) ? 0 : (size_t)b * (size_t)ND;
    const __half* Wh = g_Wh + (size_t)widx * DDIM * DDIM;

    const uint32_t asb0 = su(As);
    const uint32_t asb1 = asb0 + 9216;
    const uint32_t bsb  = su(Bs);

    // ---- stage A0 + B0 (cp.async group 0) ----
#pragma unroll
    for (int c = tid; c < 512; c += 256) {
        int r = c >> 3, q = c & 7;
        int rowg = rowbase + r; rowg = rowg < NNODE ? rowg : NNODE-1;
        cpa16(asb0 + (r*AS_STR + q*8)*2, xa + xboff + (size_t)rowg*DDIM + q*8);
    }
#pragma unroll
    for (int c = tid; c < 1024; c += 256) {
        int r = c >> 4, q = c & 15;
        cpa16(bsb + (r*BS_STR + q*8)*2, Wh + (size_t)r*DDIM + q*8);
    }
    asm volatile("cp.async.commit_group;" ::: "memory");
    // ---- stage A1 (cp.async group 1) ----
#pragma unroll
    for (int c = tid; c < 512; c += 256) {
        int r = c >> 3, q = c & 7;
        int rowg = rowbase + r; rowg = rowg < NNODE ? rowg : NNODE-1;
        cpa16(asb1 + (r*AS_STR + q*8)*2, xa + xboff + (size_t)rowg*DDIM + 64 + q*8);
    }
    asm volatile("cp.async.commit_group;" ::: "memory");

    // ---- B1 prefetch into registers (in flight during mma0) ----
    uint4 b1r[4];
#pragma unroll
    for (int i = 0; i < 4; i++) {
        int c = tid + i*256;
        int r = c >> 4, q = c & 15;
        b1r[i] = *(const uint4*)(Wh + (size_t)(64 + r)*DDIM + q*8);
    }

    // ---- stage per-column params (independent of tiles) ----
    for (int i = tid; i < 512; i += 256) {
        int a = i >> 7, c = i & 127;
        float v;
        if (MODE == 0)
            v = (a == 0) ? g_wnsW[widx*DDIM + c] :
                (a == 1) ? g_bnsW[widx*DDIM + c] :
                (a == 2) ? attS[c] : attD[c];
        else
            v = (a == 0) ? b2[c] : (a == 1) ? W3[DDIM + c] : 0.f;
        pb[i] = v;
    }

    float acc[8][4];
#pragma unroll
    for (int i = 0; i < 8; i++)
#pragma unroll
        for (int j = 0; j < 4; j++) acc[i][j] = 0.f;

    auto domma = [&](uint32_t asbX) {
#pragma unroll
        for (int ks = 0; ks < 4; ++ks) {
            uint32_t a0, a1, a2, a3;
            uint32_t aaddr = asbX + ((warpM*16 + (lane & 15))*AS_STR
                                     + ks*16 + ((lane >> 4) << 3)) * 2;
            ldsm4(a0, a1, a2, a3, aaddr);
#pragma unroll
            for (int nt = 0; nt < 4; ++nt) {
                uint32_t b0, b1, b2r, b3;
                uint32_t baddr = bsb + ((ks*16 + (lane & 15))*BS_STR
                                        + warpN*64 + nt*16 + ((lane >> 4) << 3)) * 2;
                ldsm4t(b0, b1, b2r, b3, baddr);
                mma16816(acc[nt*2],   a0, a1, a2, a3, b0, b1);
                mma16816(acc[nt*2+1], a0, a1, a2, a3, b2r, b3);
            }
        }
    };

    asm volatile("cp.async.wait_group 1;" ::: "memory");   // A0+B0 landed
    __syncthreads();
    domma(asb0);                                            // chunk 0
    __syncthreads();                                        // all done reading B0
#pragma unroll
    for (int i = 0; i < 4; i++) {                           // B1 regs -> smem
        int c = tid + i*256;
        int r = c >> 4, q = c & 15;
        *(uint4*)&Bs[r*BS_STR + q*8] = b1r[i];
    }
    asm volatile("cp.async.wait_group 0;" ::: "memory");    // A1 landed
    __syncthreads();
    domma(asb1);                                            // chunk 1
    __syncthreads();

    {
        int gr = warpM*16 + (lane >> 2);
        int cb0 = warpN*64 + (lane & 3)*2;
#pragma unroll
        for (int nt8 = 0; nt8 < 8; ++nt8) {
            int cb = cb0 + nt8*8;
            acc_s[gr*132 + cb]       = acc[nt8][0];
            acc_s[gr*132 + cb + 1]   = acc[nt8][1];
            acc_s[(gr+8)*132 + cb]   = acc[nt8][2];
            acc_s[(gr+8)*132 + cb+1] = acc[nt8][3];
        }
    }
    __syncthreads();

    const int r = tid >> 2, seg = tid & 3;
    const int row_g = rowbase + r;
    const int rc = row_g < NNODE ? row_g : NNODE-1;

    if (MODE == 0) {
        float st = state[(size_t)b*NNODE + rc];
        float asr = 0.f, ads = 0.f;
        uint32_t hw[16];
#pragma unroll
        for (int i2 = 0; i2 < 16; i2++) {
            int c = seg*32 + i2*2;
            float v0 = acc_s[r*132 + c]     + st*pb[c]     + pb[128 + c];
            float v1 = acc_s[r*132 + c + 1] + st*pb[c + 1] + pb[129 + c];
            asr += v0*pb[256 + c] + v1*pb[257 + c];
            ads += v0*pb[384 + c] + v1*pb[385 + c];
            __half2 h = __floats2half2_rn(v0, v1);
            hw[i2] = *(uint32_t*)&h;
        }
        asr += __shfl_xor_sync(0xffffffffu, asr, 1);
        asr += __shfl_xor_sync(0xffffffffu, asr, 2);
        ads += __shfl_xor_sync(0xffffffffu, ads, 1);
        ads += __shfl_xor_sync(0xffffffffu, ads, 2);
        if (row_g < NNODE) {
            if (seg == 0) {
                g_asrcT[row_g*4 + b] = asr;
                g_adstT[row_g*4 + b] = ads;
            }
            uint4* dst = (uint4*)(g_h + (size_t)b*ND + (size_t)row_g*DDIM + seg*32);
            const uint4* s4 = (const uint4*)hw;
            dst[0] = s4[0]; dst[1] = s4[1]; dst[2] = s4[2]; dst[3] = s4[3];
        }
    } else {
        float ra = 0.f;
#pragma unroll
        for (int i = 0; i < 32; i++) {
            int c = seg*32 + i;
            float v = fmaxf(acc_s[r*132 + c] + pb[c], 0.f);
            ra += v * pb[128 + c];
        }
        ra += __shfl_xor_sync(0xffffffffu, ra, 1);
        ra += __shfl_xor_sync(0xffffffffu, ra, 2);
        if (seg == 0 && row_g < NNODE)
            out[(size_t)b*NNODE + row_g] = g_rs[b] + ra;
    }
}

// ---------------- edge softmax + aggregate ----------------
// One warp per dst node, 4 batches fused (proven R8 core), now with:
//   - __launch_bounds__(256, 5): regs capped ~51 -> 5 blocks/SM (40 warps)
//   - grid-stride over nodes (EBLK fixed grid): no wave-quantization tail
// Layer-0 launch carries extra blocks (>= EBLK) that reset g_cur.
// LAST=1: additionally accumulate node-sum of outputs into g_semb.
__device__ __forceinline__ void edge_acc(float a, float ad, uint2 hv,
                                         float4& acc, float& s) {
    float ae = a + ad;
    ae = ae > 0.f ? ae : SLOPE*ae;
    float p = __expf(ae);
    s += p;
    union { uint2 u; __half2 h[2]; } c; c.u = hv;
    float2 f0 = __half22float2(c.h[0]);
    float2 f1 = __half22float2(c.h[1]);
    acc.x += p*f0.x; acc.y += p*f0.y;
    acc.z += p*f1.x; acc.w += p*f1.y;
}

template<int LAST>
__global__ void __launch_bounds__(256, 5) k_edge(const float* __restrict__ bias) {
    __shared__ float sacc[BNUM*DDIM];
    if (LAST) {
        sacc[threadIdx.x] = 0.f;
        sacc[threadIdx.x + 256] = 0.f;
        __syncthreads();
    }
    int lane = threadIdx.x & 31;
    if (blockIdx.x < EBLK) {
        int wid0 = (blockIdx.x*blockDim.x + threadIdx.x) >> 5;
        for (int n = wid0; n < NNODE; n += EBLK*8) {
            int e0 = g_offs[n], e1 = g_offs[n+1];
            const float4 ad = *(const float4*)&g_adstT[n*4];

            float4 acc0 = {0,0,0,0}, acc1 = {0,0,0,0}, acc2 = {0,0,0,0}, acc3 = {0,0,0,0};
            float s0 = 0.f, s1 = 0.f, s2 = 0.f, s3 = 0.f;

            // depth-2 pipeline
            int sv = __ldg(&g_srcs[e0]);
            float4 as = *(const float4*)&g_asrcT[sv*4];
            const __half* hr = g_h + (size_t)sv*DDIM + lane*4;
            uint2 h0 = *(const uint2*)(hr);
            uint2 h1 = *(const uint2*)(hr + ND);
            uint2 h2 = *(const uint2*)(hr + 2*(size_t)ND);
            uint2 h3 = *(const uint2*)(hr + 3*(size_t)ND);

            for (int e = e0; e < e1; ++e) {
                float4 asc = as;
                uint2 c0 = h0, c1 = h1, c2 = h2, c3 = h3;
                if (e + 1 < e1) {
                    sv = __ldg(&g_srcs[e+1]);
                    as = *(const float4*)&g_asrcT[sv*4];
                    hr = g_h + (size_t)sv*DDIM + lane*4;
                    h0 = *(const uint2*)(hr);
                    h1 = *(const uint2*)(hr + ND);
                    h2 = *(const uint2*)(hr + 2*(size_t)ND);
                    h3 = *(const uint2*)(hr + 3*(size_t)ND);
                }
                edge_acc(asc.x, ad.x, c0, acc0, s0);
                edge_acc(asc.y, ad.y, c1, acc1, s1);
                edge_acc(asc.z, ad.z, c2, acc2, s2);
                edge_acc(asc.w, ad.w, c3, acc3, s3);
            }

            float4 bi = ((const float4*)bias)[lane];
            float4* accs[4] = {&acc0, &acc1, &acc2, &acc3};
            float ss[4] = {s0, s1, s2, s3};
#pragma unroll
            for (int b = 0; b < 4; b++) {
                float inv = 1.f / ss[b];
                float4 a = *accs[b];
                float o0 = fmaxf(a.x*inv + bi.x, 0.f);
                float o1 = fmaxf(a.y*inv + bi.y, 0.f);
                float o2 = fmaxf(a.z*inv + bi.z, 0.f);
                float o3 = fmaxf(a.w*inv + bi.w, 0.f);
                union { uint2 u; __half2 h[2]; } ov;
                ov.h[0] = __floats2half2_rn(o0, o1);
                ov.h[1] = __floats2half2_rn(o2, o3);
                *(uint2*)(g_xh + (size_t)b*ND + (size_t)n*DDIM + lane*4) = ov.u;
                if (LAST) {
                    int cb = b*DDIM + lane*4;
                    atomicAdd(&sacc[cb],     o0);
                    atomicAdd(&sacc[cb + 1], o1);
                    atomicAdd(&sacc[cb + 2], o2);
                    atomicAdd(&sacc[cb + 3], o3);
                }
            }
        }
    } else {
        // cur-reset role (extra blocks on the layer-0 launch only)
        int idx = (blockIdx.x - EBLK)*256 + threadIdx.x;
        if (idx < NNODE) g_cur[idx] = 0;
    }
    if (LAST) {
        __syncthreads();
        atomicAdd(&g_semb[threadIdx.x],       sacc[threadIdx.x]);
        atomicAdd(&g_semb[threadIdx.x + 256], sacc[threadIdx.x + 256]);
    }
}

// ---------------- final head ----------------
__global__ void k_beta(const float* __restrict__ W1, const float* __restrict__ b1,
                       const float* __restrict__ W3, const float* __restrict__ b3) {
    int b = blockIdx.x, d = threadIdx.x;
    __shared__ float semb[DDIM];
    semb[d] = g_semb[b*DDIM + d];
    __syncthreads();
    float acc = b1[d];
    for (int k = 0; k < DDIM; k++) acc += semb[k] * W1[k*DDIM + d];
    float v = fmaxf(acc, 0.f) * W3[d];
    __shared__ float sh[DDIM];
    sh[d] = v; __syncthreads();
    for (int off = 64; off > 0; off >>= 1) {
        if (d < off) sh[d] += sh[d+off];
        __syncthreads();
    }
    if (d == 0) g_rs[b] = sh[0] + b3[0];
}

// ---------------- launch ----------------
extern "C" void kernel_launch(void* const* d_in, const int* in_sizes, int n_in,
                              void* d_out, int out_size) {
    const float* state = (const float*)d_in[0];
    const float* struc = (const float*)d_in[1];
    const int*   ei    = (const int*)d_in[2];
    const float* gatW  = (const float*)d_in[3];
    const float* attS  = (const float*)d_in[4];
    const float* attD  = (const float*)d_in[5];
    const float* Wns   = (const float*)d_in[6];
    const float* bns   = (const float*)d_in[7];
    const float* bias  = (const float*)d_in[8];
    const float* W1    = (const float*)d_in[9];
    const float* b1    = (const float*)d_in[10];
    const float* W2    = (const float*)d_in[11];
    const float* b2    = (const float*)d_in[12];
    const float* W3    = (const float*)d_in[13];
    const float* b3    = (const float*)d_in[14];
    float* out = (float*)d_out;
    int Etot = in_sizes[2] / 2;

    // L1: init (prep + semb zero + fp16 conversions) fused with CSR histogram
    k_init<<<1319 + (Etot + 255)/256, 256>>>(gatW, W2, Wns, bns, struc, ei, Etot);
    // L2: prefix scan
    k_scan<<<1, 1024>>>(Etot);

    dim3 g0(GEMMX + (Etot + 1023)/1024, BNUM);   // gemm0 + scatter fused
    dim3 gg(GEMMX, BNUM);
    const int egrid0 = EBLK + 40;                // + g_cur reset tail

    k_gemm<0><<<g0, 256>>>(0, state, attS, attD, nullptr, nullptr, nullptr, ei, Etot);
    k_edge<0><<<egrid0, 256>>>(bias);
    k_gemm<0><<<gg, 256>>>(1, state, attS + DDIM, attD + DDIM, nullptr, nullptr, nullptr, ei, Etot);
    k_edge<0><<<EBLK, 256>>>(bias + DDIM);
    k_gemm<0><<<gg, 256>>>(2, state, attS + 2*DDIM, attD + 2*DDIM, nullptr, nullptr, nullptr, ei, Etot);
    k_edge<1><<<EBLK, 256>>>(bias + 2*DDIM);

    k_beta<<<BNUM, 128>>>(W1, b1, W3, b3);
    k_gemm<1><<<gg, 256>>>(3, state, nullptr, nullptr, b2, W3, out, ei, Etot);
}

// round 15
// speedup vs baseline: 1.2287x; 1.2287x over previous
#include <cuda_runtime.h>
#include <cuda_fp16.h>
#include <cstdint>

#define NNODE 10000
#define BNUM  4
#define DDIM  128
#define ECAP  262144
#define ND    (NNODE*DDIM)
#define SLOPE 0.01f
#define GEMMX 157   // (NNODE+63)/64
#define EBLK  592   // edge grid: 148 SMs x 4 blocks (single wave, grid-stride)

// ---------------- scratch (device globals; no allocation) ----------------
__device__ __align__(16) __half g_xh[BNUM*ND];   // layer activations (fp16, per-batch)
__device__ __align__(16) __half g_strh[ND];      // strucEmb fp16
__device__ __align__(16) __half g_Wh[4*DDIM*DDIM]; // gatW[0..2], W2 as fp16
__device__ __align__(16) __half g_h[BNUM*ND];    // per-layer hidden h (fp16, per-batch)
__device__ __align__(16) float g_asrcT[NNODE*4]; // [n][b] transposed logits
__device__ __align__(16) float g_adstT[NNODE*4];
__device__ int   g_offs[NNODE+1];
__device__ int   g_cur[NNODE];    // ==0 at entry of every execution (reset by edge0 tail)
__device__ int   g_srcs[ECAP];
__device__ float g_wnsW[3*DDIM];
__device__ float g_bnsW[3*DDIM];
__device__ float g_semb[BNUM*DDIM];
__device__ float g_rs[BNUM];

// ---------------- mma / async helpers ----------------
__device__ __forceinline__ uint32_t su(const void* p) {
    return (uint32_t)__cvta_generic_to_shared(p);
}
__device__ __forceinline__ void cpa16(uint32_t dst, const void* src) {
    asm volatile("cp.async.cg.shared.global [%0], [%1], 16;" :: "r"(dst), "l"(src));
}
__device__ __forceinline__ void ldsm4(uint32_t& r0, uint32_t& r1, uint32_t& r2,
                                      uint32_t& r3, uint32_t addr) {
    asm volatile("ldmatrix.sync.aligned.m8n8.x4.shared.b16 {%0,%1,%2,%3}, [%4];"
                 : "=r"(r0), "=r"(r1), "=r"(r2), "=r"(r3) : "r"(addr));
}
__device__ __forceinline__ void ldsm4t(uint32_t& r0, uint32_t& r1, uint32_t& r2,
                                       uint32_t& r3, uint32_t addr) {
    asm volatile("ldmatrix.sync.aligned.m8n8.x4.trans.shared.b16 {%0,%1,%2,%3}, [%4];"
                 : "=r"(r0), "=r"(r1), "=r"(r2), "=r"(r3) : "r"(addr));
}
__device__ __forceinline__ void mma16816(float* c, uint32_t a0, uint32_t a1,
                                         uint32_t a2, uint32_t a3,
                                         uint32_t b0, uint32_t b1) {
    asm volatile(
        "mma.sync.aligned.m16n8k16.row.col.f32.f16.f16.f32 "
        "{%0,%1,%2,%3}, {%4,%5,%6,%7}, {%8,%9}, {%0,%1,%2,%3};"
        : "+f"(c[0]), "+f"(c[1]), "+f"(c[2]), "+f"(c[3])
        : "r"(a0), "r"(a1), "r"(a2), "r"(a3), "r"(b0), "r"(b1));
}

// ---------------- init: prep + semb zero + fp16 conversions + HIST fused ----
__global__ void k_init(const float* __restrict__ W, const float* __restrict__ W2,
                       const float* __restrict__ Wns, const float* __restrict__ bns,
                       const float* __restrict__ struc,
                       const int* __restrict__ ei, int Etot) {
    int bb = blockIdx.x;
    if (bb < 3) {
        int l = bb, c = threadIdx.x;
        if (c < DDIM) {
            const float* Wl = W + l*DDIM*DDIM;
            float aw = 0.f, ab = 0.f;
            for (int k = 0; k < DDIM; k++) {
                float w = Wl[k*DDIM + c];
                aw += Wns[l*DDIM + k]*w;
                ab += bns[l*DDIM + k]*w;
            }
            g_wnsW[l*DDIM + c] = aw;
            g_bnsW[l*DDIM + c] = ab;
        }
    } else if (bb < 5) {
        int i = (bb - 3)*256 + threadIdx.x;
        if (i < BNUM*DDIM) g_semb[i] = 0.f;
    } else if (bb < 69) {
        int i0 = (bb - 5)*1024 + threadIdx.x*4;
        int m = i0 >> 14, off = i0 & 16383;
        const float* src = (m < 3) ? (W + m*16384 + off) : (W2 + off);
        float4 v = *(const float4*)src;
        union { __half2 h[2]; uint2 u; } cv;
        cv.h[0] = __floats2half2_rn(v.x, v.y);
        cv.h[1] = __floats2half2_rn(v.z, v.w);
        *(uint2*)&g_Wh[i0] = cv.u;
    } else if (bb < 1319) {
        int i0 = (bb - 69)*1024 + threadIdx.x*4;
        if (i0 < ND) {
            float4 v = *(const float4*)(struc + i0);
            union { __half2 h[2]; uint2 u; } cv;
            cv.h[0] = __floats2half2_rn(v.x, v.y);
            cv.h[1] = __floats2half2_rn(v.z, v.w);
            *(uint2*)&g_strh[i0] = cv.u;
        }
    } else {
        // histogram role (g_cur == 0 at entry: static init / edge0-tail reset)
        int e = (bb - 1319)*256 + threadIdx.x;
        if (e < Etot) atomicAdd(&g_cur[ei[Etot + e]], 1);
    }
}

// ---------------- CSR scan ----------------
__global__ void k_scan(int Etot) {
    __shared__ int sh[1024];
    const int ITEMS = 10;
    int t = threadIdx.x;
    int base = t*ITEMS;
    int loc[ITEMS]; int sum = 0;
#pragma unroll
    for (int i = 0; i < ITEMS; i++) {
        int idx = base + i;
        int v = (idx < NNODE) ? g_cur[idx] : 0;
        loc[i] = sum; sum += v;
    }
    sh[t] = sum; __syncthreads();
    for (int off = 1; off < 1024; off <<= 1) {
        int v = (t >= off) ? sh[t-off] : 0;
        __syncthreads();
        sh[t] += v;
        __syncthreads();
    }
    int pre = t ? sh[t-1] : 0;
#pragma unroll
    for (int i = 0; i < ITEMS; i++) {
        int idx = base + i;
        if (idx < NNODE) { int o = pre + loc[i]; g_offs[idx] = o; g_cur[idx] = o; }
    }
    if (t == 1023) g_offs[NNODE] = sh[1023];
}

// ---------------- HMMA GEMM (64x128 tile, fp16 in / fp32 acc) ----------------
// Software-pipelined: cp.async group{A0,B0}, group{A1}; B1 prefetched to regs
// during mma0. Layer-0 launch carries extra blocks doing CSR scatter.
#define AS_STR 72
#define BS_STR 136
template<int MODE>
__global__ void __launch_bounds__(256)
k_gemm(int widx, const float* __restrict__ state,
       const float* __restrict__ attS, const float* __restrict__ attD,
       const float* __restrict__ b2, const float* __restrict__ W3,
       float* __restrict__ out,
       const int* __restrict__ ei, int Etot) {
    if (blockIdx.x >= GEMMX) {
        // scatter role (only present on the layer-0 launch; needs k_scan done)
        int e = ((blockIdx.x - GEMMX)*4 + blockIdx.y)*256 + threadIdx.x;
        if (e < Etot) {
            int d = ei[Etot + e];
            int pos = atomicAdd(&g_cur[d], 1);
            g_srcs[pos] = ei[e];
        }
        return;
    }
    __shared__ __align__(16) unsigned char smraw[37888];
    __half* As = (__half*)smraw;                    // [2][64][72]  (double buffer)
    __half* Bs = (__half*)(smraw + 18432);          // [64][136]
    float*  acc_s = (float*)smraw;                  // [64][132] (reused)
    float*  pb = (float*)(smraw + 35840);           // 512 floats of params

    const int tid = threadIdx.x;
    const int lane = tid & 31, warp = tid >> 5;
    const int warpM = warp & 3, warpN = warp >> 2;
    const int b = blockIdx.y;
    const int rowbase = blockIdx.x * 64;

    const __half* xa = (widx == 0) ? g_strh : g_xh;
    const size_t xboff = (widx == 0) ? 0 : (size_t)b * (size_t)ND;
    const __half* Wh = g_Wh + (size_t)widx * DDIM * DDIM;

    const uint32_t asb0 = su(As);
    const uint32_t asb1 = asb0 + 9216;
    const uint32_t bsb  = su(Bs);

    // ---- stage A0 + B0 (cp.async group 0) ----
#pragma unroll
    for (int c = tid; c < 512; c += 256) {
        int r = c >> 3, q = c & 7;
        int rowg = rowbase + r; rowg = rowg < NNODE ? rowg : NNODE-1;
        cpa16(asb0 + (r*AS_STR + q*8)*2, xa + xboff + (size_t)rowg*DDIM + q*8);
    }
#pragma unroll
    for (int c = tid; c < 1024; c += 256) {
        int r = c >> 4, q = c & 15;
        cpa16(bsb + (r*BS_STR + q*8)*2, Wh + (size_t)r*DDIM + q*8);
    }
    asm volatile("cp.async.commit_group;" ::: "memory");
    // ---- stage A1 (cp.async group 1) ----
#pragma unroll
    for (int c = tid; c < 512; c += 256) {
        int r = c >> 3, q = c & 7;
        int rowg = rowbase + r; rowg = rowg < NNODE ? rowg : NNODE-1;
        cpa16(asb1 + (r*AS_STR + q*8)*2, xa + xboff + (size_t)rowg*DDIM + 64 + q*8);
    }
    asm volatile("cp.async.commit_group;" ::: "memory");

    // ---- B1 prefetch into registers (in flight during mma0) ----
    uint4 b1r[4];
#pragma unroll
    for (int i = 0; i < 4; i++) {
        int c = tid + i*256;
        int r = c >> 4, q = c & 15;
        b1r[i] = *(const uint4*)(Wh + (size_t)(64 + r)*DDIM + q*8);
    }

    // ---- stage per-column params (independent of tiles) ----
    for (int i = tid; i < 512; i += 256) {
        int a = i >> 7, c = i & 127;
        float v;
        if (MODE == 0)
            v = (a == 0) ? g_wnsW[widx*DDIM + c] :
                (a == 1) ? g_bnsW[widx*DDIM + c] :
                (a == 2) ? attS[c] : attD[c];
        else
            v = (a == 0) ? b2[c] : (a == 1) ? W3[DDIM + c] : 0.f;
        pb[i] = v;
    }

    float acc[8][4];
#pragma unroll
    for (int i = 0; i < 8; i++)
#pragma unroll
        for (int j = 0; j < 4; j++) acc[i][j] = 0.f;

    auto domma = [&](uint32_t asbX) {
#pragma unroll
        for (int ks = 0; ks < 4; ++ks) {
            uint32_t a0, a1, a2, a3;
            uint32_t aaddr = asbX + ((warpM*16 + (lane & 15))*AS_STR
                                     + ks*16 + ((lane >> 4) << 3)) * 2;
            ldsm4(a0, a1, a2, a3, aaddr);
#pragma unroll
            for (int nt = 0; nt < 4; ++nt) {
                uint32_t b0, b1, b2r, b3;
                uint32_t baddr = bsb + ((ks*16 + (lane & 15))*BS_STR
                                        + warpN*64 + nt*16 + ((lane >> 4) << 3)) * 2;
                ldsm4t(b0, b1, b2r, b3, baddr);
                mma16816(acc[nt*2],   a0, a1, a2, a3, b0, b1);
                mma16816(acc[nt*2+1], a0, a1, a2, a3, b2r, b3);
            }
        }
    };

    asm volatile("cp.async.wait_group 1;" ::: "memory");   // A0+B0 landed
    __syncthreads();
    domma(asb0);                                            // chunk 0
    __syncthreads();                                        // all done reading B0
#pragma unroll
    for (int i = 0; i < 4; i++) {                           // B1 regs -> smem
        int c = tid + i*256;
        int r = c >> 4, q = c & 15;
        *(uint4*)&Bs[r*BS_STR + q*8] = b1r[i];
    }
    asm volatile("cp.async.wait_group 0;" ::: "memory");    // A1 landed
    __syncthreads();
    domma(asb1);                                            // chunk 1
    __syncthreads();

    {
        int gr = warpM*16 + (lane >> 2);
        int cb0 = warpN*64 + (lane & 3)*2;
#pragma unroll
        for (int nt8 = 0; nt8 < 8; ++nt8) {
            int cb = cb0 + nt8*8;
            acc_s[gr*132 + cb]       = acc[nt8][0];
            acc_s[gr*132 + cb + 1]   = acc[nt8][1];
            acc_s[(gr+8)*132 + cb]   = acc[nt8][2];
            acc_s[(gr+8)*132 + cb+1] = acc[nt8][3];
        }
    }
    __syncthreads();

    const int r = tid >> 2, seg = tid & 3;
    const int row_g = rowbase + r;
    const int rc = row_g < NNODE ? row_g : NNODE-1;

    if (MODE == 0) {
        float st = state[(size_t)b*NNODE + rc];
        float asr = 0.f, ads = 0.f;
        uint32_t hw[16];
#pragma unroll
        for (int i2 = 0; i2 < 16; i2++) {
            int c = seg*32 + i2*2;
            float v0 = acc_s[r*132 + c]     + st*pb[c]     + pb[128 + c];
            float v1 = acc_s[r*132 + c + 1] + st*pb[c + 1] + pb[129 + c];
            asr += v0*pb[256 + c] + v1*pb[257 + c];
            ads += v0*pb[384 + c] + v1*pb[385 + c];
            __half2 h = __floats2half2_rn(v0, v1);
            hw[i2] = *(uint32_t*)&h;
        }
        asr += __shfl_xor_sync(0xffffffffu, asr, 1);
        asr += __shfl_xor_sync(0xffffffffu, asr, 2);
        ads += __shfl_xor_sync(0xffffffffu, ads, 1);
        ads += __shfl_xor_sync(0xffffffffu, ads, 2);
        if (row_g < NNODE) {
            if (seg == 0) {
                g_asrcT[row_g*4 + b] = asr;
                g_adstT[row_g*4 + b] = ads;
            }
            uint4* dst = (uint4*)(g_h + (size_t)b*ND + (size_t)row_g*DDIM + seg*32);
            const uint4* s4 = (const uint4*)hw;
            dst[0] = s4[0]; dst[1] = s4[1]; dst[2] = s4[2]; dst[3] = s4[3];
        }
    } else {
        float ra = 0.f;
#pragma unroll
        for (int i = 0; i < 32; i++) {
            int c = seg*32 + i;
            float v = fmaxf(acc_s[r*132 + c] + pb[c], 0.f);
            ra += v * pb[128 + c];
        }
        ra += __shfl_xor_sync(0xffffffffu, ra, 1);
        ra += __shfl_xor_sync(0xffffffffu, ra, 2);
        if (seg == 0 && row_g < NNODE)
            out[(size_t)b*NNODE + row_g] = g_rs[b] + ra;
    }
}

// ---------------- edge softmax + aggregate ----------------
// One warp per dst node, 4 batches fused (proven R8 core).
// Single-wave grid (EBLK=592) + grid-stride over nodes: no wave-quantization
// tail, NO register cap (R14 lesson: reg cap spills the pipeline).
// Layer-0 launch carries extra blocks (>= EBLK) that reset g_cur.
// LAST=1: additionally accumulate node-sum of outputs into g_semb.
__device__ __forceinline__ void edge_acc(float a, float ad, uint2 hv,
                                         float4& acc, float& s) {
    float ae = a + ad;
    ae = ae > 0.f ? ae : SLOPE*ae;
    float p = __expf(ae);
    s += p;
    union { uint2 u; __half2 h[2]; } c; c.u = hv;
    float2 f0 = __half22float2(c.h[0]);
    float2 f1 = __half22float2(c.h[1]);
    acc.x += p*f0.x; acc.y += p*f0.y;
    acc.z += p*f1.x; acc.w += p*f1.y;
}

template<int LAST>
__global__ void __launch_bounds__(256) k_edge(const float* __restrict__ bias) {
    __shared__ float sacc[BNUM*DDIM];
    if (LAST) {
        sacc[threadIdx.x] = 0.f;
        sacc[threadIdx.x + 256] = 0.f;
        __syncthreads();
    }
    int lane = threadIdx.x & 31;
    if (blockIdx.x < EBLK) {
        int wid0 = (blockIdx.x*blockDim.x + threadIdx.x) >> 5;
        for (int n = wid0; n < NNODE; n += EBLK*8) {
            int e0 = g_offs[n], e1 = g_offs[n+1];
            const float4 ad = *(const float4*)&g_adstT[n*4];

            float4 acc0 = {0,0,0,0}, acc1 = {0,0,0,0}, acc2 = {0,0,0,0}, acc3 = {0,0,0,0};
            float s0 = 0.f, s1 = 0.f, s2 = 0.f, s3 = 0.f;

            // depth-2 pipeline
            int sv = __ldg(&g_srcs[e0]);
            float4 as = *(const float4*)&g_asrcT[sv*4];
            const __half* hr = g_h + (size_t)sv*DDIM + lane*4;
            uint2 h0 = *(const uint2*)(hr);
            uint2 h1 = *(const uint2*)(hr + ND);
            uint2 h2 = *(const uint2*)(hr + 2*(size_t)ND);
            uint2 h3 = *(const uint2*)(hr + 3*(size_t)ND);

            for (int e = e0; e < e1; ++e) {
                float4 asc = as;
                uint2 c0 = h0, c1 = h1, c2 = h2, c3 = h3;
                if (e + 1 < e1) {
                    sv = __ldg(&g_srcs[e+1]);
                    as = *(const float4*)&g_asrcT[sv*4];
                    hr = g_h + (size_t)sv*DDIM + lane*4;
                    h0 = *(const uint2*)(hr);
                    h1 = *(const uint2*)(hr + ND);
                    h2 = *(const uint2*)(hr + 2*(size_t)ND);
                    h3 = *(const uint2*)(hr + 3*(size_t)ND);
                }
                edge_acc(asc.x, ad.x, c0, acc0, s0);
                edge_acc(asc.y, ad.y, c1, acc1, s1);
                edge_acc(asc.z, ad.z, c2, acc2, s2);
                edge_acc(asc.w, ad.w, c3, acc3, s3);
            }

            float4 bi = ((const float4*)bias)[lane];
            float4* accs[4] = {&acc0, &acc1, &acc2, &acc3};
            float ss[4] = {s0, s1, s2, s3};
#pragma unroll
            for (int b = 0; b < 4; b++) {
                float inv = 1.f / ss[b];
                float4 a = *accs[b];
                float o0 = fmaxf(a.x*inv + bi.x, 0.f);
                float o1 = fmaxf(a.y*inv + bi.y, 0.f);
                float o2 = fmaxf(a.z*inv + bi.z, 0.f);
                float o3 = fmaxf(a.w*inv + bi.w, 0.f);
                union { uint2 u; __half2 h[2]; } ov;
                ov.h[0] = __floats2half2_rn(o0, o1);
                ov.h[1] = __floats2half2_rn(o2, o3);
                *(uint2*)(g_xh + (size_t)b*ND + (size_t)n*DDIM + lane*4) = ov.u;
                if (LAST) {
                    int cb = b*DDIM + lane*4;
                    atomicAdd(&sacc[cb],     o0);
                    atomicAdd(&sacc[cb + 1], o1);
                    atomicAdd(&sacc[cb + 2], o2);
                    atomicAdd(&sacc[cb + 3], o3);
                }
            }
        }
    } else {
        // cur-reset role (extra blocks on the layer-0 launch only)
        int idx = (blockIdx.x - EBLK)*256 + threadIdx.x;
        if (idx < NNODE) g_cur[idx] = 0;
    }
    if (LAST) {
        __syncthreads();
        atomicAdd(&g_semb[threadIdx.x],       sacc[threadIdx.x]);
        atomicAdd(&g_semb[threadIdx.x + 256], sacc[threadIdx.x + 256]);
    }
}

// ---------------- final head ----------------
__global__ void k_beta(const float* __restrict__ W1, const float* __restrict__ b1,
                       const float* __restrict__ W3, const float* __restrict__ b3) {
    int b = blockIdx.x, d = threadIdx.x;
    __shared__ float semb[DDIM];
    semb[d] = g_semb[b*DDIM + d];
    __syncthreads();
    float acc = b1[d];
    for (int k = 0; k < DDIM; k++) acc += semb[k] * W1[k*DDIM + d];
    float v = fmaxf(acc, 0.f) * W3[d];
    __shared__ float sh[DDIM];
    sh[d] = v; __syncthreads();
    for (int off = 64; off > 0; off >>= 1) {
        if (d < off) sh[d] += sh[d+off];
        __syncthreads();
    }
    if (d == 0) g_rs[b] = sh[0] + b3[0];
}

// ---------------- launch ----------------
extern "C" void kernel_launch(void* const* d_in, const int* in_sizes, int n_in,
                              void* d_out, int out_size) {
    const float* state = (const float*)d_in[0];
    const float* struc = (const float*)d_in[1];
    const int*   ei    = (const int*)d_in[2];
    const float* gatW  = (const float*)d_in[3];
    const float* attS  = (const float*)d_in[4];
    const float* attD  = (const float*)d_in[5];
    const float* Wns   = (const float*)d_in[6];
    const float* bns   = (const float*)d_in[7];
    const float* bias  = (const float*)d_in[8];
    const float* W1    = (const float*)d_in[9];
    const float* b1    = (const float*)d_in[10];
    const float* W2    = (const float*)d_in[11];
    const float* b2    = (const float*)d_in[12];
    const float* W3    = (const float*)d_in[13];
    const float* b3    = (const float*)d_in[14];
    float* out = (float*)d_out;
    int Etot = in_sizes[2] / 2;

    // L1: init (prep + semb zero + fp16 conversions) fused with CSR histogram
    k_init<<<1319 + (Etot + 255)/256, 256>>>(gatW, W2, Wns, bns, struc, ei, Etot);
    // L2: prefix scan
    k_scan<<<1, 1024>>>(Etot);

    dim3 g0(GEMMX + (Etot + 1023)/1024, BNUM);   // gemm0 + scatter fused
    dim3 gg(GEMMX, BNUM);
    const int egrid0 = EBLK + 40;                // + g_cur reset tail

    k_gemm<0><<<g0, 256>>>(0, state, attS, attD, nullptr, nullptr, nullptr, ei, Etot);
    k_edge<0><<<egrid0, 256>>>(bias);
    k_gemm<0><<<gg, 256>>>(1, state, attS + DDIM, attD + DDIM, nullptr, nullptr, nullptr, ei, Etot);
    k_edge<0><<<EBLK, 256>>>(bias + DDIM);
    k_gemm<0><<<gg, 256>>>(2, state, attS + 2*DDIM, attD + 2*DDIM, nullptr, nullptr, nullptr, ei, Etot);
    k_edge<1><<<EBLK, 256>>>(bias + 2*DDIM);

    k_beta<<<BNUM, 128>>>(W1, b1, W3, b3);
    k_gemm<1><<<gg, 256>>>(3, state, nullptr, nullptr, b2, W3, out, ei, Etot);
}

// round 16
// speedup vs baseline: 1.3031x; 1.0606x over previous
#include <cuda_runtime.h>
#include <cuda_fp16.h>
#include <cstdint>

#define NNODE 10000
#define BNUM  4
#define DDIM  128
#define ECAP  262144
#define ND    (NNODE*DDIM)
#define SLOPE 0.01f
#define GEMMX 157   // (NNODE+63)/64
#define EBLK  592   // edge grid: 148 SMs x 4 blocks (single wave, grid-stride)

// ---------------- scratch (device globals; no allocation) ----------------
__device__ __align__(16) __half g_xh[BNUM*ND];   // layer activations (fp16, per-batch)
__device__ __align__(16) __half g_strh[ND];      // strucEmb fp16
__device__ __align__(16) __half g_Wh[4*DDIM*DDIM]; // gatW[0..2], W2 as fp16
__device__ __align__(16) __half g_h[BNUM*ND];    // per-layer hidden h (fp16, per-batch)
__device__ __align__(16) float g_asrcT[NNODE*4]; // [n][b] transposed logits
__device__ __align__(16) float g_adstT[NNODE*4];
__device__ int   g_offs[NNODE+1];
__device__ int   g_cur[NNODE];    // ==0 at entry of every execution (reset by edge0 tail)
__device__ int   g_srcs[ECAP];
__device__ float g_wnsW[3*DDIM];
__device__ float g_bnsW[3*DDIM];
__device__ float g_semb[BNUM*DDIM];
__device__ float g_rs[BNUM];

// ---------------- mma / async helpers ----------------
__device__ __forceinline__ uint32_t su(const void* p) {
    return (uint32_t)__cvta_generic_to_shared(p);
}
__device__ __forceinline__ void cpa16(uint32_t dst, const void* src) {
    asm volatile("cp.async.cg.shared.global [%0], [%1], 16;" :: "r"(dst), "l"(src));
}
__device__ __forceinline__ void ldsm4(uint32_t& r0, uint32_t& r1, uint32_t& r2,
                                      uint32_t& r3, uint32_t addr) {
    asm volatile("ldmatrix.sync.aligned.m8n8.x4.shared.b16 {%0,%1,%2,%3}, [%4];"
                 : "=r"(r0), "=r"(r1), "=r"(r2), "=r"(r3) : "r"(addr));
}
__device__ __forceinline__ void ldsm4t(uint32_t& r0, uint32_t& r1, uint32_t& r2,
                                       uint32_t& r3, uint32_t addr) {
    asm volatile("ldmatrix.sync.aligned.m8n8.x4.trans.shared.b16 {%0,%1,%2,%3}, [%4];"
                 : "=r"(r0), "=r"(r1), "=r"(r2), "=r"(r3) : "r"(addr));
}
__device__ __forceinline__ void mma16816(float* c, uint32_t a0, uint32_t a1,
                                         uint32_t a2, uint32_t a3,
                                         uint32_t b0, uint32_t b1) {
    asm volatile(
        "mma.sync.aligned.m16n8k16.row.col.f32.f16.f16.f32 "
        "{%0,%1,%2,%3}, {%4,%5,%6,%7}, {%8,%9}, {%0,%1,%2,%3};"
        : "+f"(c[0]), "+f"(c[1]), "+f"(c[2]), "+f"(c[3])
        : "r"(a0), "r"(a1), "r"(a2), "r"(a3), "r"(b0), "r"(b1));
}

// ---------------- init: prep + semb zero + fp16 conversions ----------------
__global__ void k_init(const float* __restrict__ W, const float* __restrict__ W2,
                       const float* __restrict__ Wns, const float* __restrict__ bns,
                       const float* __restrict__ struc) {
    int bb = blockIdx.x;
    if (bb < 3) {
        int l = bb, c = threadIdx.x;
        if (c < DDIM) {
            const float* Wl = W + l*DDIM*DDIM;
            float aw = 0.f, ab = 0.f;
            for (int k = 0; k < DDIM; k++) {
                float w = Wl[k*DDIM + c];
                aw += Wns[l*DDIM + k]*w;
                ab += bns[l*DDIM + k]*w;
            }
            g_wnsW[l*DDIM + c] = aw;
            g_bnsW[l*DDIM + c] = ab;
        }
    } else if (bb < 5) {
        int i = (bb - 3)*256 + threadIdx.x;
        if (i < BNUM*DDIM) g_semb[i] = 0.f;
    } else if (bb < 69) {
        int i0 = (bb - 5)*1024 + threadIdx.x*4;
        int m = i0 >> 14, off = i0 & 16383;
        const float* src = (m < 3) ? (W + m*16384 + off) : (W2 + off);
        float4 v = *(const float4*)src;
        union { __half2 h[2]; uint2 u; } cv;
        cv.h[0] = __floats2half2_rn(v.x, v.y);
        cv.h[1] = __floats2half2_rn(v.z, v.w);
        *(uint2*)&g_Wh[i0] = cv.u;
    } else {
        int i0 = (bb - 69)*1024 + threadIdx.x*4;
        if (i0 < ND) {
            float4 v = *(const float4*)(struc + i0);
            union { __half2 h[2]; uint2 u; } cv;
            cv.h[0] = __floats2half2_rn(v.x, v.y);
            cv.h[1] = __floats2half2_rn(v.z, v.w);
            *(uint2*)&g_strh[i0] = cv.u;
        }
    }
}

// ---------------- CSR build (side stream: hist -> scan -> scatter) ---------
__global__ void k_hist(const int* __restrict__ ei, int Etot) {
    int e = blockIdx.x*blockDim.x + threadIdx.x;
    if (e < Etot) atomicAdd(&g_cur[ei[Etot + e]], 1);
}
__global__ void k_scan(int Etot) {
    __shared__ int sh[1024];
    const int ITEMS = 10;
    int t = threadIdx.x;
    int base = t*ITEMS;
    int loc[ITEMS]; int sum = 0;
#pragma unroll
    for (int i = 0; i < ITEMS; i++) {
        int idx = base + i;
        int v = (idx < NNODE) ? g_cur[idx] : 0;
        loc[i] = sum; sum += v;
    }
    sh[t] = sum; __syncthreads();
    for (int off = 1; off < 1024; off <<= 1) {
        int v = (t >= off) ? sh[t-off] : 0;
        __syncthreads();
        sh[t] += v;
        __syncthreads();
    }
    int pre = t ? sh[t-1] : 0;
#pragma unroll
    for (int i = 0; i < ITEMS; i++) {
        int idx = base + i;
        if (idx < NNODE) { int o = pre + loc[i]; g_offs[idx] = o; g_cur[idx] = o; }
    }
    if (t == 1023) g_offs[NNODE] = sh[1023];
}
__global__ void k_scatter(const int* __restrict__ ei, int Etot) {
    int e = blockIdx.x*blockDim.x + threadIdx.x;
    if (e < Etot) {
        int d = ei[Etot + e];
        int pos = atomicAdd(&g_cur[d], 1);
        g_srcs[pos] = ei[e];
    }
}

// ---------------- HMMA GEMM (64x128 tile, fp16 in / fp32 acc) ----------------
// Software-pipelined: cp.async group{A0,B0}, group{A1}; B1 prefetched to regs.
#define AS_STR 72
#define BS_STR 136
template<int MODE>
__global__ void __launch_bounds__(256)
k_gemm(int widx, const float* __restrict__ state,
       const float* __restrict__ attS, const float* __restrict__ attD,
       const float* __restrict__ b2, const float* __restrict__ W3,
       float* __restrict__ out) {
    __shared__ __align__(16) unsigned char smraw[37888];
    __half* As = (__half*)smraw;                    // [2][64][72]  (double buffer)
    __half* Bs = (__half*)(smraw + 18432);          // [64][136]
    float*  acc_s = (float*)smraw;                  // [64][132] (reused)
    float*  pb = (float*)(smraw + 35840);           // 512 floats of params

    const int tid = threadIdx.x;
    const int lane = tid & 31, warp = tid >> 5;
    const int warpM = warp & 3, warpN = warp >> 2;
    const int b = blockIdx.y;
    const int rowbase = blockIdx.x * 64;

    const __half* xa = (widx == 0) ? g_strh : g_xh;
    const size_t xboff = (widx == 0) ? 0 : (size_t)b * (size_t)ND;
    const __half* Wh = g_Wh + (size_t)widx * DDIM * DDIM;

    const uint32_t asb0 = su(As);
    const uint32_t asb1 = asb0 + 9216;
    const uint32_t bsb  = su(Bs);

    // ---- stage A0 + B0 (cp.async group 0) ----
#pragma unroll
    for (int c = tid; c < 512; c += 256) {
        int r = c >> 3, q = c & 7;
        int rowg = rowbase + r; rowg = rowg < NNODE ? rowg : NNODE-1;
        cpa16(asb0 + (r*AS_STR + q*8)*2, xa + xboff + (size_t)rowg*DDIM + q*8);
    }
#pragma unroll
    for (int c = tid; c < 1024; c += 256) {
        int r = c >> 4, q = c & 15;
        cpa16(bsb + (r*BS_STR + q*8)*2, Wh + (size_t)r*DDIM + q*8);
    }
    asm volatile("cp.async.commit_group;" ::: "memory");
    // ---- stage A1 (cp.async group 1) ----
#pragma unroll
    for (int c = tid; c < 512; c += 256) {
        int r = c >> 3, q = c & 7;
        int rowg = rowbase + r; rowg = rowg < NNODE ? rowg : NNODE-1;
        cpa16(asb1 + (r*AS_STR + q*8)*2, xa + xboff + (size_t)rowg*DDIM + 64 + q*8);
    }
    asm volatile("cp.async.commit_group;" ::: "memory");

    // ---- B1 prefetch into registers (in flight during mma0) ----
    uint4 b1r[4];
#pragma unroll
    for (int i = 0; i < 4; i++) {
        int c = tid + i*256;
        int r = c >> 4, q = c & 15;
        b1r[i] = *(const uint4*)(Wh + (size_t)(64 + r)*DDIM + q*8);
    }

    // ---- stage per-column params (independent of tiles) ----
    for (int i = tid; i < 512; i += 256) {
        int a = i >> 7, c = i & 127;
        float v;
        if (MODE == 0)
            v = (a == 0) ? g_wnsW[widx*DDIM + c] :
                (a == 1) ? g_bnsW[widx*DDIM + c] :
                (a == 2) ? attS[c] : attD[c];
        else
            v = (a == 0) ? b2[c] : (a == 1) ? W3[DDIM + c] : 0.f;
        pb[i] = v;
    }

    float acc[8][4];
#pragma unroll
    for (int i = 0; i < 8; i++)
#pragma unroll
        for (int j = 0; j < 4; j++) acc[i][j] = 0.f;

    auto domma = [&](uint32_t asbX) {
#pragma unroll
        for (int ks = 0; ks < 4; ++ks) {
            uint32_t a0, a1, a2, a3;
            uint32_t aaddr = asbX + ((warpM*16 + (lane & 15))*AS_STR
                                     + ks*16 + ((lane >> 4) << 3)) * 2;
            ldsm4(a0, a1, a2, a3, aaddr);
#pragma unroll
            for (int nt = 0; nt < 4; ++nt) {
                uint32_t b0, b1, b2r, b3;
                uint32_t baddr = bsb + ((ks*16 + (lane & 15))*BS_STR
                                        + warpN*64 + nt*16 + ((lane >> 4) << 3)) * 2;
                ldsm4t(b0, b1, b2r, b3, baddr);
                mma16816(acc[nt*2],   a0, a1, a2, a3, b0, b1);
                mma16816(acc[nt*2+1], a0, a1, a2, a3, b2r, b3);
            }
        }
    };

    asm volatile("cp.async.wait_group 1;" ::: "memory");   // A0+B0 landed
    __syncthreads();
    domma(asb0);                                            // chunk 0
    __syncthreads();                                        // all done reading B0
#pragma unroll
    for (int i = 0; i < 4; i++) {                           // B1 regs -> smem
        int c = tid + i*256;
        int r = c >> 4, q = c & 15;
        *(uint4*)&Bs[r*BS_STR + q*8] = b1r[i];
    }
    asm volatile("cp.async.wait_group 0;" ::: "memory");    // A1 landed
    __syncthreads();
    domma(asb1);                                            // chunk 1
    __syncthreads();

    {
        int gr = warpM*16 + (lane >> 2);
        int cb0 = warpN*64 + (lane & 3)*2;
#pragma unroll
        for (int nt8 = 0; nt8 < 8; ++nt8) {
            int cb = cb0 + nt8*8;
            acc_s[gr*132 + cb]       = acc[nt8][0];
            acc_s[gr*132 + cb + 1]   = acc[nt8][1];
            acc_s[(gr+8)*132 + cb]   = acc[nt8][2];
            acc_s[(gr+8)*132 + cb+1] = acc[nt8][3];
        }
    }
    __syncthreads();

    const int r = tid >> 2, seg = tid & 3;
    const int row_g = rowbase + r;
    const int rc = row_g < NNODE ? row_g : NNODE-1;

    if (MODE == 0) {
        float st = state[(size_t)b*NNODE + rc];
        float asr = 0.f, ads = 0.f;
        uint32_t hw[16];
#pragma unroll
        for (int i2 = 0; i2 < 16; i2++) {
            int c = seg*32 + i2*2;
            float v0 = acc_s[r*132 + c]     + st*pb[c]     + pb[128 + c];
            float v1 = acc_s[r*132 + c + 1] + st*pb[c + 1] + pb[129 + c];
            asr += v0*pb[256 + c] + v1*pb[257 + c];
            ads += v0*pb[384 + c] + v1*pb[385 + c];
            __half2 h = __floats2half2_rn(v0, v1);
            hw[i2] = *(uint32_t*)&h;
        }
        asr += __shfl_xor_sync(0xffffffffu, asr, 1);
        asr += __shfl_xor_sync(0xffffffffu, asr, 2);
        ads += __shfl_xor_sync(0xffffffffu, ads, 1);
        ads += __shfl_xor_sync(0xffffffffu, ads, 2);
        if (row_g < NNODE) {
            if (seg == 0) {
                g_asrcT[row_g*4 + b] = asr;
                g_adstT[row_g*4 + b] = ads;
            }
            uint4* dst = (uint4*)(g_h + (size_t)b*ND + (size_t)row_g*DDIM + seg*32);
            const uint4* s4 = (const uint4*)hw;
            dst[0] = s4[0]; dst[1] = s4[1]; dst[2] = s4[2]; dst[3] = s4[3];
        }
    } else {
        float ra = 0.f;
#pragma unroll
        for (int i = 0; i < 32; i++) {
            int c = seg*32 + i;
            float v = fmaxf(acc_s[r*132 + c] + pb[c], 0.f);
            ra += v * pb[128 + c];
        }
        ra += __shfl_xor_sync(0xffffffffu, ra, 1);
        ra += __shfl_xor_sync(0xffffffffu, ra, 2);
        if (seg == 0 && row_g < NNODE)
            out[(size_t)b*NNODE + row_g] = g_rs[b] + ra;
    }
}

// ---------------- edge softmax + aggregate ----------------
// One warp per dst node, 4 batches fused (proven R8 core).
// Single-wave grid (EBLK=592) + grid-stride; no register cap.
// Layer-0 launch carries extra blocks (>= EBLK) that reset g_cur.
// LAST=1: node-sum into PER-WARP smem slices (plain adds, no per-node
// atomics), cross-slice reduce + one global atomic per thread at block end.
__device__ __forceinline__ void edge_acc(float a, float ad, uint2 hv,
                                         float4& acc, float& s) {
    float ae = a + ad;
    ae = ae > 0.f ? ae : SLOPE*ae;
    float p = __expf(ae);
    s += p;
    union { uint2 u; __half2 h[2]; } c; c.u = hv;
    float2 f0 = __half22float2(c.h[0]);
    float2 f1 = __half22float2(c.h[1]);
    acc.x += p*f0.x; acc.y += p*f0.y;
    acc.z += p*f1.x; acc.w += p*f1.y;
}

template<int LAST>
__global__ void __launch_bounds__(256) k_edge(const float* __restrict__ bias) {
    extern __shared__ float sacc[];   // LAST only: [8 warps][512]
    int lane = threadIdx.x & 31;
    int wloc = threadIdx.x >> 5;
    if (LAST) {
        for (int i = threadIdx.x; i < 8*512; i += 256) sacc[i] = 0.f;
        __syncthreads();
    }
    if (blockIdx.x < EBLK) {
        float* ws = LAST ? (sacc + wloc*512) : nullptr;
        int wid0 = (blockIdx.x*blockDim.x + threadIdx.x) >> 5;
        for (int n = wid0; n < NNODE; n += EBLK*8) {
            int e0 = g_offs[n], e1 = g_offs[n+1];
            const float4 ad = *(const float4*)&g_adstT[n*4];

            float4 acc0 = {0,0,0,0}, acc1 = {0,0,0,0}, acc2 = {0,0,0,0}, acc3 = {0,0,0,0};
            float s0 = 0.f, s1 = 0.f, s2 = 0.f, s3 = 0.f;

            // depth-2 pipeline
            int sv = __ldg(&g_srcs[e0]);
            float4 as = *(const float4*)&g_asrcT[sv*4];
            const __half* hr = g_h + (size_t)sv*DDIM + lane*4;
            uint2 h0 = *(const uint2*)(hr);
            uint2 h1 = *(const uint2*)(hr + ND);
            uint2 h2 = *(const uint2*)(hr + 2*(size_t)ND);
            uint2 h3 = *(const uint2*)(hr + 3*(size_t)ND);

            for (int e = e0; e < e1; ++e) {
                float4 asc = as;
                uint2 c0 = h0, c1 = h1, c2 = h2, c3 = h3;
                if (e + 1 < e1) {
                    sv = __ldg(&g_srcs[e+1]);
                    as = *(const float4*)&g_asrcT[sv*4];
                    hr = g_h + (size_t)sv*DDIM + lane*4;
                    h0 = *(const uint2*)(hr);
                    h1 = *(const uint2*)(hr + ND);
                    h2 = *(const uint2*)(hr + 2*(size_t)ND);
                    h3 = *(const uint2*)(hr + 3*(size_t)ND);
                }
                edge_acc(asc.x, ad.x, c0, acc0, s0);
                edge_acc(asc.y, ad.y, c1, acc1, s1);
                edge_acc(asc.z, ad.z, c2, acc2, s2);
                edge_acc(asc.w, ad.w, c3, acc3, s3);
            }

            float4 bi = ((const float4*)bias)[lane];
            float4* accs[4] = {&acc0, &acc1, &acc2, &acc3};
            float ss[4] = {s0, s1, s2, s3};
#pragma unroll
            for (int b = 0; b < 4; b++) {
                float inv = 1.f / ss[b];
                float4 a = *accs[b];
                float o0 = fmaxf(a.x*inv + bi.x, 0.f);
                float o1 = fmaxf(a.y*inv + bi.y, 0.f);
                float o2 = fmaxf(a.z*inv + bi.z, 0.f);
                float o3 = fmaxf(a.w*inv + bi.w, 0.f);
                union { uint2 u; __half2 h[2]; } ov;
                ov.h[0] = __floats2half2_rn(o0, o1);
                ov.h[1] = __floats2half2_rn(o2, o3);
                *(uint2*)(g_xh + (size_t)b*ND + (size_t)n*DDIM + lane*4) = ov.u;
                if (LAST) {
                    int cb = b*DDIM + lane*4;
                    ws[cb]     += o0;
                    ws[cb + 1] += o1;
                    ws[cb + 2] += o2;
                    ws[cb + 3] += o3;
                }
            }
        }
    } else {
        // cur-reset role (extra blocks on the layer-0 launch only)
        int idx = (blockIdx.x - EBLK)*256 + threadIdx.x;
        if (idx < NNODE) g_cur[idx] = 0;
    }
    if (LAST) {
        __syncthreads();
        // reduce 8 warp slices -> global (2 columns per thread)
#pragma unroll
        for (int q = 0; q < 2; q++) {
            int col = threadIdx.x + q*256;
            float v = 0.f;
#pragma unroll
            for (int w = 0; w < 8; w++) v += sacc[w*512 + col];
            atomicAdd(&g_semb[col], v);
        }
    }
}

// ---------------- final head ----------------
__global__ void k_beta(const float* __restrict__ W1, const float* __restrict__ b1,
                       const float* __restrict__ W3, const float* __restrict__ b3) {
    int b = blockIdx.x, d = threadIdx.x;
    __shared__ float semb[DDIM];
    semb[d] = g_semb[b*DDIM + d];
    __syncthreads();
    float acc = b1[d];
    for (int k = 0; k < DDIM; k++) acc += semb[k] * W1[k*DDIM + d];
    float v = fmaxf(acc, 0.f) * W3[d];
    __shared__ float sh[DDIM];
    sh[d] = v; __syncthreads();
    for (int off = 64; off > 0; off >>= 1) {
        if (d < off) sh[d] += sh[d+off];
        __syncthreads();
    }
    if (d == 0) g_rs[b] = sh[0] + b3[0];
}

// ---------------- launch ----------------
extern "C" void kernel_launch(void* const* d_in, const int* in_sizes, int n_in,
                              void* d_out, int out_size) {
    const float* state = (const float*)d_in[0];
    const float* struc = (const float*)d_in[1];
    const int*   ei    = (const int*)d_in[2];
    const float* gatW  = (const float*)d_in[3];
    const float* attS  = (const float*)d_in[4];
    const float* attD  = (const float*)d_in[5];
    const float* Wns   = (const float*)d_in[6];
    const float* bns   = (const float*)d_in[7];
    const float* bias  = (const float*)d_in[8];
    const float* W1    = (const float*)d_in[9];
    const float* b1    = (const float*)d_in[10];
    const float* W2    = (const float*)d_in[11];
    const float* b2    = (const float*)d_in[12];
    const float* W3    = (const float*)d_in[13];
    const float* b3    = (const float*)d_in[14];
    float* out = (float*)d_out;
    int Etot = in_sizes[2] / 2;

    // persistent side stream + events (created once, on the first non-capture call)
    static cudaStream_t s_side = nullptr;
    static cudaEvent_t ev_fork = nullptr, ev_join = nullptr;
    if (!s_side) {
        cudaStreamCreateWithFlags(&s_side, cudaStreamNonBlocking);
        cudaEventCreateWithFlags(&ev_fork, cudaEventDisableTiming);
        cudaEventCreateWithFlags(&ev_join, cudaEventDisableTiming);
    }

    // fork: CSR build (hist -> scan -> scatter) on side stream,
    // overlapped with init + gemm0 on the main stream.
    cudaEventRecord(ev_fork, 0);
    cudaStreamWaitEvent(s_side, ev_fork, 0);
    k_hist<<<(Etot + 255)/256, 256, 0, s_side>>>(ei, Etot);
    k_scan<<<1, 1024, 0, s_side>>>(Etot);
    k_scatter<<<(Etot + 255)/256, 256, 0, s_side>>>(ei, Etot);
    cudaEventRecord(ev_join, s_side);

    k_init<<<1319, 256>>>(gatW, W2, Wns, bns, struc);

    dim3 gg(GEMMX, BNUM);
    const int egrid0 = EBLK + 40;                // + g_cur reset tail
    const int SACC_B = 8*512*(int)sizeof(float); // LAST smem

    k_gemm<0><<<gg, 256>>>(0, state, attS, attD, nullptr, nullptr, nullptr);
    cudaStreamWaitEvent(0, ev_join, 0);          // join CSR before edge0
    k_edge<0><<<egrid0, 256>>>(bias);
    k_gemm<0><<<gg, 256>>>(1, state, attS + DDIM, attD + DDIM, nullptr, nullptr, nullptr);
    k_edge<0><<<EBLK, 256>>>(bias + DDIM);
    k_gemm<0><<<gg, 256>>>(2, state, attS + 2*DDIM, attD + 2*DDIM, nullptr, nullptr, nullptr);
    k_edge<1><<<EBLK, 256, SACC_B>>>(bias + 2*DDIM);

    k_beta<<<BNUM, 128>>>(W1, b1, W3, b3);
    k_gemm<1><<<gg, 256>>>(3, state, nullptr, nullptr, b2, W3, out);
}